// round 1
// baseline (speedup 1.0000x reference)
#include <cuda_runtime.h>
#include <cstdint>

#define BATCH 4
#define S_LEN 2048
#define HID   1024
#define NHEAD 16
#define HDIM  64

// Scratch for Q,K,V in [B][NH][S][HD] layout (33.5 MB each). __device__ globals:
// allowed scratch (no runtime allocation).
__device__ float g_q[(size_t)BATCH * NHEAD * S_LEN * HDIM];
__device__ float g_k[(size_t)BATCH * NHEAD * S_LEN * HDIM];
__device__ float g_v[(size_t)BATCH * NHEAD * S_LEN * HDIM];

// Round-to-nearest fp32 -> tf32 (unbiased; truncation would bias dot products).
__device__ __forceinline__ uint32_t f2tf32(float x) {
    uint32_t u;
    asm("cvt.rna.tf32.f32 %0, %1;" : "=r"(u) : "f"(x));
    return u;
}

// m16n8k8 tf32 MMA, D = A*B + D. Standard Ampere fragment layouts:
// A: a0=(g,t) a1=(g+8,t) a2=(g,t+4) a3=(g+8,t+4)   [g=lane>>2, t=lane&3]
// B: b0=(k=t,n=g) b1=(k=t+4,n=g)
// C: c0=(g,2t) c1=(g,2t+1) c2=(g+8,2t) c3=(g+8,2t+1)
__device__ __forceinline__ void mma_tf32(float* c, const uint32_t* a, const uint32_t* b) {
    asm volatile(
        "mma.sync.aligned.m16n8k8.row.col.f32.tf32.tf32.f32 "
        "{%0,%1,%2,%3}, {%4,%5,%6,%7}, {%8,%9}, {%0,%1,%2,%3};"
        : "+f"(c[0]), "+f"(c[1]), "+f"(c[2]), "+f"(c[3])
        : "r"(a[0]), "r"(a[1]), "r"(a[2]), "r"(a[3]), "r"(b[0]), "r"(b[1]));
}

// ---------------------------------------------------------------------------
// Kernel 1: fused QKV projection.  C[m][n] = sum_k X[m][k] * W[n][k] + bias[n]
// X: [8192][1024], W: [1024][1024] (K-major => natural layout is B-col-major).
// Block tile 128x128, K-tile 32, 256 threads = 8 warps (2x4), warp tile 64x32.
// Output scattered directly into [B][NH][S][HD] scratch.
// ---------------------------------------------------------------------------
__global__ __launch_bounds__(256)
void qkv_gemm_kernel(const float* __restrict__ X,
                     const float* __restrict__ Wq, const float* __restrict__ bq,
                     const float* __restrict__ Wk, const float* __restrict__ bk,
                     const float* __restrict__ Wv, const float* __restrict__ bv) {
    __shared__ float As[128][36];   // [m][k], pad 36 -> frag LDS conflict-free (banks 4g+t)
    __shared__ float Bs[128][36];   // [n][k]

    const int which = blockIdx.z;
    const float* W    = (which == 0) ? Wq : (which == 1) ? Wk : Wv;
    const float* bias = (which == 0) ? bq : (which == 1) ? bk : bv;
    float* O          = (which == 0) ? g_q : (which == 1) ? g_k : g_v;

    const int bm = blockIdx.y * 128;
    const int bn = blockIdx.x * 128;
    const int tid  = threadIdx.x;
    const int warp = tid >> 5, lane = tid & 31;
    const int g = lane >> 2, t = lane & 3;
    const int wm = (warp >> 2) * 64;   // warp row offset within block: 0 / 64
    const int wn = (warp & 3) * 32;    // warp col offset: 0/32/64/96

    float c[4][4][4];
#pragma unroll
    for (int mf = 0; mf < 4; mf++)
#pragma unroll
        for (int nf = 0; nf < 4; nf++)
#pragma unroll
            for (int r = 0; r < 4; r++) c[mf][nf][r] = 0.f;

    for (int k0 = 0; k0 < HID; k0 += 32) {
        // Stage A and B tiles (128x32 each), converting to tf32 bits.
#pragma unroll
        for (int i = 0; i < 4; i++) {
            int idx = i * 256 + tid;        // 0..1023 float4s
            int row = idx >> 3;             // 0..127
            int k4  = (idx & 7) << 2;       // 0,4,...,28
            float4 va = *reinterpret_cast<const float4*>(X + (size_t)(bm + row) * HID + k0 + k4);
            float4 vb = *reinterpret_cast<const float4*>(W + (size_t)(bn + row) * HID + k0 + k4);
            float4 wa, wb;
            wa.x = __uint_as_float(f2tf32(va.x)); wa.y = __uint_as_float(f2tf32(va.y));
            wa.z = __uint_as_float(f2tf32(va.z)); wa.w = __uint_as_float(f2tf32(va.w));
            wb.x = __uint_as_float(f2tf32(vb.x)); wb.y = __uint_as_float(f2tf32(vb.y));
            wb.z = __uint_as_float(f2tf32(vb.z)); wb.w = __uint_as_float(f2tf32(vb.w));
            *reinterpret_cast<float4*>(&As[row][k4]) = wa;
            *reinterpret_cast<float4*>(&Bs[row][k4]) = wb;
        }
        __syncthreads();

#pragma unroll
        for (int ks = 0; ks < 4; ks++) {
            uint32_t a[4][4], bb[4][2];
#pragma unroll
            for (int mf = 0; mf < 4; mf++) {
                int r0 = wm + mf * 16;
                a[mf][0] = __float_as_uint(As[r0 + g    ][ks * 8 + t]);
                a[mf][1] = __float_as_uint(As[r0 + g + 8][ks * 8 + t]);
                a[mf][2] = __float_as_uint(As[r0 + g    ][ks * 8 + t + 4]);
                a[mf][3] = __float_as_uint(As[r0 + g + 8][ks * 8 + t + 4]);
            }
#pragma unroll
            for (int nf = 0; nf < 4; nf++) {
                int n0 = wn + nf * 8;
                bb[nf][0] = __float_as_uint(Bs[n0 + g][ks * 8 + t]);
                bb[nf][1] = __float_as_uint(Bs[n0 + g][ks * 8 + t + 4]);
            }
#pragma unroll
            for (int mf = 0; mf < 4; mf++)
#pragma unroll
                for (int nf = 0; nf < 4; nf++) mma_tf32(c[mf][nf], a[mf], bb[nf]);
        }
        __syncthreads();
    }

    // Epilogue: col n -> (head, d); row m -> (b, s); write [B][NH][S][HD].
#pragma unroll
    for (int mf = 0; mf < 4; mf++) {
#pragma unroll
        for (int nf = 0; nf < 4; nf++) {
            int row = bm + wm + mf * 16 + g;
            int col = bn + wn + nf * 8 + 2 * t;
            float b0v = bias[col], b1v = bias[col + 1];
            int b  = row >> 11;
            int s  = row & (S_LEN - 1);
            int hh = col >> 6;
            int d  = col & (HDIM - 1);
            float* p0 = O + ((size_t)((b * NHEAD + hh) * S_LEN + s)) * HDIM + d;
            *reinterpret_cast<float2*>(p0) =
                make_float2(c[mf][nf][0] + b0v, c[mf][nf][1] + b1v);
            // row+8 lives at s+8 (same b: block tile is 128-aligned in s).
            *reinterpret_cast<float2*>(p0 + 8 * HDIM) =
                make_float2(c[mf][nf][2] + b0v, c[mf][nf][3] + b1v);
        }
    }
}

// Stage a 64x64 fp32 tile (row stride 64 in gmem) into smem [64][68], tf32-rounded.
__device__ __forceinline__ void stage_tile64(float dst[64][68],
                                             const float* __restrict__ src, int tid) {
#pragma unroll
    for (int i = 0; i < 8; i++) {
        int idx = i * 128 + tid;        // 0..1023 float4s
        int row = idx >> 4;             // 0..63
        int c4  = (idx & 15) << 2;      // 0..60
        float4 v = *reinterpret_cast<const float4*>(src + (size_t)row * HDIM + c4);
        float4 w;
        w.x = __uint_as_float(f2tf32(v.x)); w.y = __uint_as_float(f2tf32(v.y));
        w.z = __uint_as_float(f2tf32(v.z)); w.w = __uint_as_float(f2tf32(v.w));
        *reinterpret_cast<float4*>(&dst[row][c4]) = w;   // stride 68*4=272B, 16B aligned
    }
}

// ---------------------------------------------------------------------------
// Kernel 2: flash attention, tf32 MMA.
// Block = 64 queries of one (b,h); 4 warps x 16 query rows (softmax warp-local).
// Q resident in registers. K and V time-share one smem tile. P re-fragmented
// (C-layout -> A-layout) via per-warp smem round-trip.
// ---------------------------------------------------------------------------
__global__ __launch_bounds__(128)
void attn_kernel(const float* __restrict__ mask, float* __restrict__ out) {
    __shared__ float KVs[64][68];       // K tile, then V tile (time-shared)
    __shared__ float Ps[4][16][68];     // per-warp P scratch

    const int qt = blockIdx.x, h = blockIdx.y, b = blockIdx.z;
    const size_t bh = ((size_t)b * NHEAD + h) * S_LEN * HDIM;
    const float* Qp = g_q + bh + (size_t)qt * 64 * HDIM;
    const float* Kp = g_k + bh;
    const float* Vp = g_v + bh;
    const float* mp = mask + (size_t)b * S_LEN;

    const int tid = threadIdx.x, warp = tid >> 5, lane = tid & 31;
    const int g = lane >> 2, t = lane & 3;

    // Load Q once into registers (A-fragments for all 8 k-steps).
    stage_tile64(KVs, Qp, tid);
    __syncthreads();
    uint32_t qa[8][4];
#pragma unroll
    for (int ks = 0; ks < 8; ks++) {
        int r0 = warp * 16;
        qa[ks][0] = __float_as_uint(KVs[r0 + g    ][ks * 8 + t]);
        qa[ks][1] = __float_as_uint(KVs[r0 + g + 8][ks * 8 + t]);
        qa[ks][2] = __float_as_uint(KVs[r0 + g    ][ks * 8 + t + 4]);
        qa[ks][3] = __float_as_uint(KVs[r0 + g + 8][ks * 8 + t + 4]);
    }
    __syncthreads();

    float o[8][4];
#pragma unroll
    for (int nf = 0; nf < 8; nf++)
#pragma unroll
        for (int r = 0; r < 4; r++) o[nf][r] = 0.f;
    float m0 = -INFINITY, m1 = -INFINITY, l0 = 0.f, l1 = 0.f;

    for (int kt = 0; kt < S_LEN / 64; kt++) {
        // ---- scores = Q . K^T ----
        stage_tile64(KVs, Kp + (size_t)kt * 64 * HDIM, tid);
        __syncthreads();
        float s[8][4];
#pragma unroll
        for (int nf = 0; nf < 8; nf++)
#pragma unroll
            for (int r = 0; r < 4; r++) s[nf][r] = 0.f;
#pragma unroll
        for (int ks = 0; ks < 8; ks++) {
#pragma unroll
            for (int nf = 0; nf < 8; nf++) {
                uint32_t bb[2];
                bb[0] = __float_as_uint(KVs[nf * 8 + g][ks * 8 + t]);
                bb[1] = __float_as_uint(KVs[nf * 8 + g][ks * 8 + t + 4]);
                mma_tf32(s[nf], qa[ks], bb);
            }
        }

        // ---- scale + mask + online softmax (rows g and g+8, warp-local) ----
        float rm0 = -INFINITY, rm1 = -INFINITY;
#pragma unroll
        for (int nf = 0; nf < 8; nf++) {
            int col = kt * 64 + nf * 8 + 2 * t;
            float mk0 = mp[col], mk1 = mp[col + 1];
            s[nf][0] = fmaf(s[nf][0], 0.125f, mk0);
            s[nf][1] = fmaf(s[nf][1], 0.125f, mk1);
            s[nf][2] = fmaf(s[nf][2], 0.125f, mk0);
            s[nf][3] = fmaf(s[nf][3], 0.125f, mk1);
            rm0 = fmaxf(rm0, fmaxf(s[nf][0], s[nf][1]));
            rm1 = fmaxf(rm1, fmaxf(s[nf][2], s[nf][3]));
        }
        rm0 = fmaxf(rm0, __shfl_xor_sync(0xffffffffu, rm0, 1));
        rm0 = fmaxf(rm0, __shfl_xor_sync(0xffffffffu, rm0, 2));
        rm1 = fmaxf(rm1, __shfl_xor_sync(0xffffffffu, rm1, 1));
        rm1 = fmaxf(rm1, __shfl_xor_sync(0xffffffffu, rm1, 2));

        float mn0 = fmaxf(m0, rm0), mn1 = fmaxf(m1, rm1);
        float al0 = __expf(m0 - mn0), al1 = __expf(m1 - mn1);
        float rs0 = 0.f, rs1 = 0.f;
#pragma unroll
        for (int nf = 0; nf < 8; nf++) {
            float p0 = __expf(s[nf][0] - mn0);
            float p1 = __expf(s[nf][1] - mn0);
            float p2 = __expf(s[nf][2] - mn1);
            float p3 = __expf(s[nf][3] - mn1);
            rs0 += p0 + p1;
            rs1 += p2 + p3;
            Ps[warp][g    ][nf * 8 + 2 * t    ] = __uint_as_float(f2tf32(p0));
            Ps[warp][g    ][nf * 8 + 2 * t + 1] = __uint_as_float(f2tf32(p1));
            Ps[warp][g + 8][nf * 8 + 2 * t    ] = __uint_as_float(f2tf32(p2));
            Ps[warp][g + 8][nf * 8 + 2 * t + 1] = __uint_as_float(f2tf32(p3));
        }
        rs0 += __shfl_xor_sync(0xffffffffu, rs0, 1);
        rs0 += __shfl_xor_sync(0xffffffffu, rs0, 2);
        rs1 += __shfl_xor_sync(0xffffffffu, rs1, 1);
        rs1 += __shfl_xor_sync(0xffffffffu, rs1, 2);
        l0 = l0 * al0 + rs0;
        l1 = l1 * al1 + rs1;
        m0 = mn0;
        m1 = mn1;
#pragma unroll
        for (int nf = 0; nf < 8; nf++) {
            o[nf][0] *= al0; o[nf][1] *= al0;
            o[nf][2] *= al1; o[nf][3] *= al1;
        }

        // ---- O += P . V (V replaces K in the shared tile) ----
        __syncthreads();                                   // all warps done with K
        stage_tile64(KVs, Vp + (size_t)kt * 64 * HDIM, tid);
        __syncthreads();
#pragma unroll
        for (int ks = 0; ks < 8; ks++) {
            uint32_t pa[4];
            pa[0] = __float_as_uint(Ps[warp][g    ][ks * 8 + t]);
            pa[1] = __float_as_uint(Ps[warp][g + 8][ks * 8 + t]);
            pa[2] = __float_as_uint(Ps[warp][g    ][ks * 8 + t + 4]);
            pa[3] = __float_as_uint(Ps[warp][g + 8][ks * 8 + t + 4]);
#pragma unroll
            for (int nf = 0; nf < 8; nf++) {
                uint32_t vb[2];
                vb[0] = __float_as_uint(KVs[ks * 8 + t    ][nf * 8 + g]);
                vb[1] = __float_as_uint(KVs[ks * 8 + t + 4][nf * 8 + g]);
                mma_tf32(o[nf], pa, vb);
            }
        }
        __syncthreads();                                   // all warps done with V
    }

    // ---- epilogue: O /= l, write [B][S][H] ----
    float inv0 = 1.f / l0, inv1 = 1.f / l1;
    int r0 = qt * 64 + warp * 16 + g;
#pragma unroll
    for (int nf = 0; nf < 8; nf++) {
        int col = h * HDIM + nf * 8 + 2 * t;
        *reinterpret_cast<float2*>(out + ((size_t)b * S_LEN + r0) * HID + col) =
            make_float2(o[nf][0] * inv0, o[nf][1] * inv0);
        *reinterpret_cast<float2*>(out + ((size_t)b * S_LEN + r0 + 8) * HID + col) =
            make_float2(o[nf][2] * inv1, o[nf][3] * inv1);
    }
}

extern "C" void kernel_launch(void* const* d_in, const int* in_sizes, int n_in,
                              void* d_out, int out_size) {
    (void)in_sizes; (void)n_in; (void)out_size;
    const float* X    = (const float*)d_in[0];
    const float* mask = (const float*)d_in[1];
    const float* Wq   = (const float*)d_in[2];
    const float* bq   = (const float*)d_in[3];
    const float* Wk   = (const float*)d_in[4];
    const float* bk   = (const float*)d_in[5];
    const float* Wv   = (const float*)d_in[6];
    const float* bv   = (const float*)d_in[7];
    float* out = (float*)d_out;

    dim3 gq(HID / 128, (BATCH * S_LEN) / 128, 3);   // 8 x 64 x 3 blocks
    qkv_gemm_kernel<<<gq, 256>>>(X, Wq, bq, Wk, bk, Wv, bv);

    dim3 ga(S_LEN / 64, NHEAD, BATCH);              // 32 x 16 x 4 blocks
    attn_kernel<<<ga, 128>>>(mask, out);
}

// round 2
// speedup vs baseline: 1.2183x; 1.2183x over previous
#include <cuda_runtime.h>
#include <cstdint>

#define BATCH 4
#define S_LEN 2048
#define HID   1024
#define NHEAD 16
#define HDIM  64

// Q/K/V scratch in MMA-fragment-packed tf32 layout (see index math in the
// epilogue of kernel 1 / loads of kernel 2). 33.5 MB each, __device__ globals.
__device__ float4 g_q4[(size_t)BATCH * NHEAD * S_LEN * HDIM / 4];
__device__ float4 g_k4[(size_t)BATCH * NHEAD * S_LEN * HDIM / 4];
__device__ float4 g_v4[(size_t)BATCH * NHEAD * S_LEN * HDIM / 4];

// Round-to-nearest fp32 -> tf32 (unbiased).
__device__ __forceinline__ uint32_t f2tf32(float x) {
    uint32_t u;
    asm("cvt.rna.tf32.f32 %0, %1;" : "=r"(u) : "f"(x));
    return u;
}

// m16n8k8 tf32 MMA, D = A*B + D. Fragment layouts (g=lane>>2, t=lane&3):
// A: a0=(g,t) a1=(g+8,t) a2=(g,t+4) a3=(g+8,t+4)
// B: b0=(k=t,n=g) b1=(k=t+4,n=g)
// C: c0=(g,2t) c1=(g,2t+1) c2=(g+8,2t) c3=(g+8,2t+1)
__device__ __forceinline__ void mma_tf32(float* c, uint32_t a0, uint32_t a1,
                                         uint32_t a2, uint32_t a3,
                                         uint32_t b0, uint32_t b1) {
    asm volatile(
        "mma.sync.aligned.m16n8k8.row.col.f32.tf32.tf32.f32 "
        "{%0,%1,%2,%3}, {%4,%5,%6,%7}, {%8,%9}, {%0,%1,%2,%3};"
        : "+f"(c[0]), "+f"(c[1]), "+f"(c[2]), "+f"(c[3])
        : "r"(a0), "r"(a1), "r"(a2), "r"(a3), "r"(b0), "r"(b1));
}

// ---------------------------------------------------------------------------
// Kernel 1: fused QKV projection. C[m][n] = sum_k X[m][k]*W[n][k] + bias[n].
// Mainloop identical to R1 (128x128x32 tiles, tf32). Epilogue scatters into
// fragment-packed gmem layouts consumed by the attention kernel:
//
// Q (A-operand, scale 1/8 folded): chunk(b,h,qc=s>>5,mf=(s>>4)&1,ks=d>>3) of
//   512B; word = lane*4 + w, lane=(s&7)*4+(d&3), w=((s>>3)&1)+2*((d>>2)&1).
// K (B-operand of QK^T):  chunk(b,h,kt=s>>6,nf=(s>>3)&7,ks2=d>>4);
//   lane=(s&7)*4+(d&3), w=((d>>3)&1)*2+((d>>2)&1).
// V (B-operand of P*V):   chunk(b,h,kt=s>>6,nf=d>>3,ks2=(s>>4)&3);
//   lane=(d&7)*4+(s&3), w=((s>>3)&1)*2+((s>>2)&1).
// ---------------------------------------------------------------------------
__global__ __launch_bounds__(256)
void qkv_gemm_kernel(const float* __restrict__ X,
                     const float* __restrict__ Wq, const float* __restrict__ bq,
                     const float* __restrict__ Wk, const float* __restrict__ bk,
                     const float* __restrict__ Wv, const float* __restrict__ bv) {
    __shared__ float As[128][36];
    __shared__ float Bs[128][36];

    const int which = blockIdx.z;
    const float* W    = (which == 0) ? Wq : (which == 1) ? Wk : Wv;
    const float* bias = (which == 0) ? bq : (which == 1) ? bk : bv;
    float* O = (float*)((which == 0) ? g_q4 : (which == 1) ? g_k4 : g_v4);

    const int bm = blockIdx.y * 128;
    const int bn = blockIdx.x * 128;
    const int tid  = threadIdx.x;
    const int warp = tid >> 5, lane = tid & 31;
    const int g = lane >> 2, t = lane & 3;
    const int wm = (warp >> 2) * 64;
    const int wn = (warp & 3) * 32;

    float c[4][4][4];
#pragma unroll
    for (int mf = 0; mf < 4; mf++)
#pragma unroll
        for (int nf = 0; nf < 4; nf++)
#pragma unroll
            for (int r = 0; r < 4; r++) c[mf][nf][r] = 0.f;

    for (int k0 = 0; k0 < HID; k0 += 32) {
#pragma unroll
        for (int i = 0; i < 4; i++) {
            int idx = i * 256 + tid;
            int row = idx >> 3;
            int k4  = (idx & 7) << 2;
            float4 va = *reinterpret_cast<const float4*>(X + (size_t)(bm + row) * HID + k0 + k4);
            float4 vb = *reinterpret_cast<const float4*>(W + (size_t)(bn + row) * HID + k0 + k4);
            float4 wa, wb;
            wa.x = __uint_as_float(f2tf32(va.x)); wa.y = __uint_as_float(f2tf32(va.y));
            wa.z = __uint_as_float(f2tf32(va.z)); wa.w = __uint_as_float(f2tf32(va.w));
            wb.x = __uint_as_float(f2tf32(vb.x)); wb.y = __uint_as_float(f2tf32(vb.y));
            wb.z = __uint_as_float(f2tf32(vb.z)); wb.w = __uint_as_float(f2tf32(vb.w));
            *reinterpret_cast<float4*>(&As[row][k4]) = wa;
            *reinterpret_cast<float4*>(&Bs[row][k4]) = wb;
        }
        __syncthreads();

#pragma unroll
        for (int ks = 0; ks < 4; ks++) {
            uint32_t a[4][4], bb[4][2];
#pragma unroll
            for (int mf = 0; mf < 4; mf++) {
                int r0 = wm + mf * 16;
                a[mf][0] = __float_as_uint(As[r0 + g    ][ks * 8 + t]);
                a[mf][1] = __float_as_uint(As[r0 + g + 8][ks * 8 + t]);
                a[mf][2] = __float_as_uint(As[r0 + g    ][ks * 8 + t + 4]);
                a[mf][3] = __float_as_uint(As[r0 + g + 8][ks * 8 + t + 4]);
            }
#pragma unroll
            for (int nf = 0; nf < 4; nf++) {
                int n0 = wn + nf * 8;
                bb[nf][0] = __float_as_uint(Bs[n0 + g][ks * 8 + t]);
                bb[nf][1] = __float_as_uint(Bs[n0 + g][ks * 8 + t + 4]);
            }
#pragma unroll
            for (int mf = 0; mf < 4; mf++)
#pragma unroll
                for (int nf = 0; nf < 4; nf++)
                    mma_tf32(c[mf][nf], a[mf][0], a[mf][1], a[mf][2], a[mf][3],
                             bb[nf][0], bb[nf][1]);
        }
        __syncthreads();
    }

    // Epilogue: bias (+scale for Q), tf32 round, scatter to fragment layout.
    const float qscale = 0.125f;   // 1/sqrt(64)
#pragma unroll
    for (int mf = 0; mf < 4; mf++) {
#pragma unroll
        for (int nf = 0; nf < 4; nf++) {
            int row = bm + wm + mf * 16 + g;         // row of value c0 (g half)
            int col = bn + wn + nf * 8 + 2 * t;      // col of values c0/c2
            float b0v = bias[col], b1v = bias[col + 1];
            float v0 = c[mf][nf][0] + b0v, v1 = c[mf][nf][1] + b1v;
            float v2 = c[mf][nf][2] + b0v, v3 = c[mf][nf][3] + b1v;
            if (which == 0) { v0 *= qscale; v1 *= qscale; v2 *= qscale; v3 *= qscale; }
            uint32_t u0 = f2tf32(v0), u1 = f2tf32(v1), u2 = f2tf32(v2), u3 = f2tf32(v3);

            int b = row >> 11;
            int s = row & (S_LEN - 1);       // s&8 == 0 here (g < 8)
            int h = col >> 6;
            int d = col & (HDIM - 1);        // d&1 == 0 (col even)

            size_t a0;
            int off1, off2, off3;            // offsets of v1(col+1), v2(row+8), v3
            if (which == 0) {
                int qc = s >> 5, mfq = (s >> 4) & 1, ks = d >> 3;
                int ln = (s & 7) * 4 + (d & 3);
                int w  = 2 * ((d >> 2) & 1); // (s>>3)&1 == 0
                a0 = ((((size_t)(b * NHEAD + h) * (S_LEN / 32) + qc) * 2 + mfq) * 8 + ks) * 128
                     + ln * 4 + w;
                off1 = 4; off2 = 1; off3 = 5;
            } else if (which == 1) {
                int kt = s >> 6, nf_k = (s >> 3) & 7, ks2 = d >> 4;
                int ln = (s & 7) * 4 + (d & 3);
                int w  = ((d >> 3) & 1) * 2 + ((d >> 2) & 1);
                a0 = ((((size_t)(b * NHEAD + h) * (S_LEN / 64) + kt) * 8 + nf_k) * 4 + ks2) * 128
                     + ln * 4 + w;
                off1 = 4; off2 = 512; off3 = 516;   // row+8 -> nf_k+1 -> +512 words
            } else {
                int kt = s >> 6, ks2 = (s >> 4) & 3, nf_v = d >> 3;
                int ln = (d & 7) * 4 + (s & 3);
                int w  = ((s >> 3) & 1) * 2 + ((s >> 2) & 1);
                a0 = ((((size_t)(b * NHEAD + h) * (S_LEN / 64) + kt) * 8 + nf_v) * 4 + ks2) * 128
                     + ln * 4 + w;
                off1 = 16; off2 = 2; off3 = 18;     // col+1 -> lane+4; row+8 -> w+2
            }
            *(uint32_t*)(O + a0)        = u0;
            *(uint32_t*)(O + a0 + off1) = u1;
            *(uint32_t*)(O + a0 + off2) = u2;
            *(uint32_t*)(O + a0 + off3) = u3;
        }
    }
}

// ---------------------------------------------------------------------------
// Kernel 2: flash attention, tf32 MMA, fragment-packed operands from gmem.
// Block = 128 queries of one (b,h); 4 warps, m=32 per warp (2 row-fragments).
// No __syncthreads in the main loop: K/V fragments come via LDG (L1-shared
// across warps); P goes through warp-private smem (syncwarp only).
// ---------------------------------------------------------------------------
__global__ __launch_bounds__(128)
void attn_kernel(const float* __restrict__ mask, float* __restrict__ out) {
    // Warp-private P in A-fragment-packed layout: [warp][mf][kchunk][lane*4+w]
    __shared__ __align__(16) float Ps[4 * 2 * 8 * 128];   // 32 KB

    const int h = blockIdx.y, b = blockIdx.z;
    const int tid = threadIdx.x, warp = tid >> 5, lane = tid & 31;
    const int g = lane >> 2, t = lane & 3;

    const int bh = b * NHEAD + h;
    // Q chunk index for this warp: qc = blockIdx.x*4 + warp
    const float4* __restrict__ Qc =
        g_q4 + (((size_t)bh * (S_LEN / 32) + blockIdx.x * 4 + warp) * 2) * 8 * 32 + lane;
    const float4* __restrict__ Kb = g_k4 + ((size_t)bh * (S_LEN / 64)) * 8 * 4 * 32 + lane;
    const float4* __restrict__ Vb = g_v4 + ((size_t)bh * (S_LEN / 64)) * 8 * 4 * 32 + lane;
    const float* __restrict__ mp = mask + (size_t)b * S_LEN;

    float* Pw = Ps + warp * 2 * 8 * 128;

    float o[2][8][4];
#pragma unroll
    for (int mf = 0; mf < 2; mf++)
#pragma unroll
        for (int nf = 0; nf < 8; nf++)
#pragma unroll
            for (int r = 0; r < 4; r++) o[mf][nf][r] = 0.f;
    float mx[2][2] = {{-INFINITY, -INFINITY}, {-INFINITY, -INFINITY}};
    float lsum[2][2] = {{0.f, 0.f}, {0.f, 0.f}};

    for (int kt = 0; kt < S_LEN / 64; kt++) {
        const float4* Kt = Kb + (size_t)kt * 8 * 4 * 32;
        const float4* Vt = Vb + (size_t)kt * 8 * 4 * 32;

        // ---- scores = Qs . K^T  (Q pre-scaled by 1/8) ----
        float s[2][8][4];
#pragma unroll
        for (int mf = 0; mf < 2; mf++)
#pragma unroll
            for (int nf = 0; nf < 8; nf++)
#pragma unroll
                for (int r = 0; r < 4; r++) s[mf][nf][r] = 0.f;

#pragma unroll
        for (int ks2 = 0; ks2 < 4; ks2++) {
            uint4 qe[2], qo[2];
#pragma unroll
            for (int mf = 0; mf < 2; mf++) {
                qe[mf] = *(const uint4*)(Qc + (mf * 8 + 2 * ks2) * 32);
                qo[mf] = *(const uint4*)(Qc + (mf * 8 + 2 * ks2 + 1) * 32);
            }
#pragma unroll
            for (int nf = 0; nf < 8; nf++) {
                uint4 kb = *(const uint4*)(Kt + (nf * 4 + ks2) * 32);
#pragma unroll
                for (int mf = 0; mf < 2; mf++) {
                    mma_tf32(s[mf][nf], qe[mf].x, qe[mf].y, qe[mf].z, qe[mf].w, kb.x, kb.y);
                    mma_tf32(s[mf][nf], qo[mf].x, qo[mf].y, qo[mf].z, qo[mf].w, kb.z, kb.w);
                }
            }
        }

        // ---- mask + online softmax (rows warp-local; reduce over t via shfl) ----
#pragma unroll
        for (int nf = 0; nf < 8; nf++) {
            float2 mk = *(const float2*)(mp + kt * 64 + nf * 8 + 2 * t);
#pragma unroll
            for (int mf = 0; mf < 2; mf++) {
                s[mf][nf][0] += mk.x; s[mf][nf][1] += mk.y;
                s[mf][nf][2] += mk.x; s[mf][nf][3] += mk.y;
            }
        }

        __syncwarp();   // previous PV reads of Ps are done before we overwrite
#pragma unroll
        for (int mf = 0; mf < 2; mf++) {
            float rm0 = -INFINITY, rm1 = -INFINITY;
#pragma unroll
            for (int nf = 0; nf < 8; nf++) {
                rm0 = fmaxf(rm0, fmaxf(s[mf][nf][0], s[mf][nf][1]));
                rm1 = fmaxf(rm1, fmaxf(s[mf][nf][2], s[mf][nf][3]));
            }
            rm0 = fmaxf(rm0, __shfl_xor_sync(0xffffffffu, rm0, 1));
            rm0 = fmaxf(rm0, __shfl_xor_sync(0xffffffffu, rm0, 2));
            rm1 = fmaxf(rm1, __shfl_xor_sync(0xffffffffu, rm1, 1));
            rm1 = fmaxf(rm1, __shfl_xor_sync(0xffffffffu, rm1, 2));

            float mn0 = fmaxf(mx[mf][0], rm0), mn1 = fmaxf(mx[mf][1], rm1);
            float al0 = __expf(mx[mf][0] - mn0), al1 = __expf(mx[mf][1] - mn1);
            float rs0 = 0.f, rs1 = 0.f;

            // Ps write base for this mf: pair (p0,p2) then (p1,p3) as STS.64.
            float* Pm = Pw + mf * 8 * 128;
            int lnw = g * 4 + ((2 * t) & 3);
            int w0  = (t >= 2) ? 2 : 0;
#pragma unroll
            for (int nf = 0; nf < 8; nf++) {
                float p0 = __expf(s[mf][nf][0] - mn0);
                float p1 = __expf(s[mf][nf][1] - mn0);
                float p2 = __expf(s[mf][nf][2] - mn1);
                float p3 = __expf(s[mf][nf][3] - mn1);
                rs0 += p0 + p1;
                rs1 += p2 + p3;
                float* base = Pm + nf * 128 + lnw * 4 + w0;
                *(float2*)(base)     = make_float2(__uint_as_float(f2tf32(p0)),
                                                   __uint_as_float(f2tf32(p2)));
                *(float2*)(base + 4) = make_float2(__uint_as_float(f2tf32(p1)),
                                                   __uint_as_float(f2tf32(p3)));
            }
            rs0 += __shfl_xor_sync(0xffffffffu, rs0, 1);
            rs0 += __shfl_xor_sync(0xffffffffu, rs0, 2);
            rs1 += __shfl_xor_sync(0xffffffffu, rs1, 1);
            rs1 += __shfl_xor_sync(0xffffffffu, rs1, 2);
            lsum[mf][0] = lsum[mf][0] * al0 + rs0;
            lsum[mf][1] = lsum[mf][1] * al1 + rs1;
            mx[mf][0] = mn0; mx[mf][1] = mn1;
#pragma unroll
            for (int nf = 0; nf < 8; nf++) {
                o[mf][nf][0] *= al0; o[mf][nf][1] *= al0;
                o[mf][nf][2] *= al1; o[mf][nf][3] *= al1;
            }
        }
        __syncwarp();   // Ps writes visible to all lanes before fragment reads

        // ---- O += P . V ----
#pragma unroll
        for (int ks2 = 0; ks2 < 4; ks2++) {
            uint4 pe[2], po[2];
#pragma unroll
            for (int mf = 0; mf < 2; mf++) {
                pe[mf] = *(const uint4*)(Pw + (mf * 8 + 2 * ks2) * 128 + lane * 4);
                po[mf] = *(const uint4*)(Pw + (mf * 8 + 2 * ks2 + 1) * 128 + lane * 4);
            }
#pragma unroll
            for (int nf = 0; nf < 8; nf++) {
                uint4 vb = *(const uint4*)(Vt + (nf * 4 + ks2) * 32);
#pragma unroll
                for (int mf = 0; mf < 2; mf++) {
                    mma_tf32(o[mf][nf], pe[mf].x, pe[mf].y, pe[mf].z, pe[mf].w, vb.x, vb.y);
                    mma_tf32(o[mf][nf], po[mf].x, po[mf].y, po[mf].z, po[mf].w, vb.z, vb.w);
                }
            }
        }
    }

    // ---- epilogue: O /= l, write [B][S][H] ----
#pragma unroll
    for (int mf = 0; mf < 2; mf++) {
        float inv0 = 1.f / lsum[mf][0], inv1 = 1.f / lsum[mf][1];
        int r0 = blockIdx.x * 128 + warp * 32 + mf * 16 + g;
#pragma unroll
        for (int nf = 0; nf < 8; nf++) {
            int col = h * HDIM + nf * 8 + 2 * t;
            *reinterpret_cast<float2*>(out + ((size_t)b * S_LEN + r0) * HID + col) =
                make_float2(o[mf][nf][0] * inv0, o[mf][nf][1] * inv0);
            *reinterpret_cast<float2*>(out + ((size_t)b * S_LEN + r0 + 8) * HID + col) =
                make_float2(o[mf][nf][2] * inv1, o[mf][nf][3] * inv1);
        }
    }
}

extern "C" void kernel_launch(void* const* d_in, const int* in_sizes, int n_in,
                              void* d_out, int out_size) {
    (void)in_sizes; (void)n_in; (void)out_size;
    const float* X    = (const float*)d_in[0];
    const float* mask = (const float*)d_in[1];
    const float* Wq   = (const float*)d_in[2];
    const float* bq   = (const float*)d_in[3];
    const float* Wk   = (const float*)d_in[4];
    const float* bk   = (const float*)d_in[5];
    const float* Wv   = (const float*)d_in[6];
    const float* bv   = (const float*)d_in[7];
    float* out = (float*)d_out;

    dim3 gq(HID / 128, (BATCH * S_LEN) / 128, 3);
    qkv_gemm_kernel<<<gq, 256>>>(X, Wq, bq, Wk, bk, Wv, bv);

    dim3 ga(S_LEN / 128, NHEAD, BATCH);   // 16 x 16 x 4 blocks, 128 threads
    attn_kernel<<<ga, 128>>>(mask, out);
}